// round 15
// baseline (speedup 1.0000x reference)
#include <cuda_runtime.h>
#include <cuda_fp16.h>
#include <math.h>

#define BN 4
#define CW 32
#define RR 64
#define SP (RR*RR*RR)        // 262144
#define MD 8
#define M2 16
#define NLY 4
#define FCHN 128
#define PI2_64 0.09817477042468103f   // 2*pi/64

typedef unsigned long long u64t;
typedef unsigned int u32t;

__device__ __forceinline__ u64t pk2(float lo, float hi) {
    u64t r; asm("mov.b64 %0, {%1,%2};" : "=l"(r) : "f"(lo), "f"(hi)); return r;
}
__device__ __forceinline__ u64t dup2(float v) { return pk2(v, v); }
__device__ __forceinline__ void up2(u64t v, float& a, float& b) {
    asm("mov.b64 {%0,%1}, %2;" : "=f"(a), "=f"(b) : "l"(v));
}
__device__ __forceinline__ void fma2(u64t& d, u64t a, u64t b) {
    asm("fma.rn.f32x2 %0, %1, %2, %0;" : "+l"(d) : "l"(a), "l"(b));
}

// ---------------- scratch (static device memory; no allocation) ----------------
__device__ __half  g_x0[BN*CW*SP];              // 67 MB (fp16 activations)
__device__ __half  g_x1[BN*CW*SP];              // 67 MB
__device__ float2 g_a [BN*CW*RR*RR*MD];         // 33.5 MB
__device__ float2 g_b [BN*CW*RR*M2*MD];         // 8.4 MB
__device__ float2 g_ft[BN*CW*M2*M2*MD];         // 2 MB
__device__ float2 g_sf[BN*CW*M2*M2*MD];         // 2 MB

// precomputed twiddle tables
__device__ float2 g_twf_[64*MD];    // fwd z: (c,-s)  [ww][k]
__device__ float  g_crt_[MD*64];    // irfft z coef   [k][ww]
__device__ float  g_cit_[MD*64];
__device__ float2 g_twF_[64*M2];    // fwd y/x: (c,-s) [h][j], ky = j<8?j:j+48
__device__ float2 g_twI_[64*M2];    // inv y/x: (c, s)
__device__ float4 g_tw4F[64*M2];    // fwd packed: (c,-s, s, c)
__device__ float4 g_tw4I[64*M2];    // inv packed: (c, s,-s, c)

__global__ void k_init() {
    int t = blockIdx.x*blockDim.x + threadIdx.x;
    if (t < 512) {
        int ww = t >> 3, k = t & 7;
        float s, c; sincosf(((ww*k)&63)*PI2_64, &s, &c);
        g_twf_[t] = make_float2(c, -s);
        const float scale = 1.0f/262144.0f;
        g_crt_[k*64+ww] = (k == 0) ? scale : 2.f*scale*c;
        g_cit_[k*64+ww] = (k == 0) ? 0.f   : -2.f*scale*s;
    }
    if (t < 1024) {
        int h = t >> 4, j = t & 15;
        int ky = (j < 8) ? j : j + 48;
        float s, c; sincosf(((ky*h)&63)*PI2_64, &s, &c);
        g_twF_[t] = make_float2(c, -s);
        g_twI_[t] = make_float2(c,  s);
        g_tw4F[t] = make_float4(c, -s,  s, c);
        g_tw4I[t] = make_float4(c,  s, -s, c);
    }
}

__device__ __forceinline__ float gelu_fast(float a) {
    float z = 1.5957691216057308f * (a + 0.044715f*a*a*a);
    float e;
    asm("ex2.approx.f32 %0, %1;" : "=f"(e) : "f"(-1.4426950408889634f*z));
    float r;
    asm("rcp.approx.f32 %0, %1;" : "=f"(r) : "f"(1.0f + e));
    return a * r;
}

__device__ __forceinline__ void mma16816(float* d, u32t a0, u32t a1, u32t a2, u32t a3,
                                         u32t b0, u32t b1) {
    asm volatile(
        "mma.sync.aligned.m16n8k16.row.col.f32.f16.f16.f32 "
        "{%0,%1,%2,%3}, {%4,%5,%6,%7}, {%8,%9}, {%0,%1,%2,%3};"
        : "+f"(d[0]), "+f"(d[1]), "+f"(d[2]), "+f"(d[3])
        : "r"(a0), "r"(a1), "r"(a2), "r"(a3), "r"(b0), "r"(b1));
}

// ---------------- fc0 + fused forward-z DFT (per batch) ----------------
__global__ void k_fc0(const float* __restrict__ u, const float* __restrict__ w,
                      const float* __restrict__ bias, int b) {
    __shared__ float  su[3][64];
    __shared__ float  sw[3*CW], sb[CW];
    __shared__ float  sxo[CW][65];
    __shared__ float2 twf[64][MD];
    int tid = threadIdx.x;  // 256
    int dh = blockIdx.x;    // 4096
    for (int t = tid; t < 512; t += 256) ((float2*)twf)[t] = g_twf_[t];
    if (tid < 3*CW) sw[tid] = w[tid];
    if (tid < CW)   sb[tid] = bias[tid];
    if (tid < 192) {
        int j = tid >> 6, ww = tid & 63;
        su[j][ww] = u[((size_t)(b*3+j) << 18) + dh*64 + ww];
    }
    __syncthreads();
    {
        int ww = tid & 63, o0 = (tid >> 6)*8;
#pragma unroll
        for (int oi = 0; oi < 8; oi++) {
            int o = o0 + oi;
            float acc = sb[o] + su[0][ww]*sw[o] + su[1][ww]*sw[CW+o] + su[2][ww]*sw[2*CW+o];
            sxo[o][ww] = acc;
            g_x0[((size_t)(b*CW+o) << 18) + dh*64 + ww] = __float2half_rn(acc);
        }
    }
    __syncthreads();
    {
        int o = tid >> 3, k = tid & 7;
        u64t zacc = 0ull;
#pragma unroll
        for (int ww = 0; ww < 64; ww++)
            fma2(zacc, dup2(sxo[o][ww]), *(const u64t*)&twf[ww][k]);
        float re, im; up2(zacc, re, im);
        g_a[((size_t)((b*CW+o)*4096 + dh))*MD + k] = make_float2(re, im);
    }
}

// ---------------- forward y: 64 -> 16 modes (2 rows/block, k-pair f32x2) ----------------
__global__ void __launch_bounds__(128) k_fy(int b) {
    __shared__ float2 sa[2][64][MD];    // 8 KB
    __shared__ float4 tw4[64][M2];      // 16 KB packed (c,-s,s,c)
    int tid = threadIdx.x;  // 128
    int bcd0 = b*CW*RR + blockIdx.x*2;  // grid 1024
    for (int t = tid; t < 1024; t += 128) ((float4*)tw4)[t] = g_tw4F[t];
    const float4* src = (const float4*)(g_a + (size_t)bcd0*64*MD);
    float4* dst = (float4*)&sa[0][0][0];
    for (int t = tid; t < 512; t += 128) dst[t] = src[t];
    __syncthreads();
    int r = tid >> 6, jk = tid & 63;
    int j = jk >> 2, kp = jk & 3;
    u64t acc0 = 0ull, acc1 = 0ull;
#pragma unroll
    for (int h = 0; h < 64; h++) {
        float4 a = *(const float4*)&sa[r][h][kp*2];
        float4 t4 = tw4[h][j];
        u64t tlo = *(const u64t*)&t4.x;   // (c,-s)
        u64t thi = *(const u64t*)&t4.z;   // (s, c)
        fma2(acc0, dup2(a.x), tlo); fma2(acc0, dup2(a.y), thi);
        fma2(acc1, dup2(a.z), tlo); fma2(acc1, dup2(a.w), thi);
    }
    float re0, im0, re1, im1;
    up2(acc0, re0, im0); up2(acc1, re1, im1);
    *(float4*)&g_b[((size_t)(bcd0+r)*M2 + j)*MD + kp*2] = make_float4(re0, im0, re1, im1);
}

// ---------------- forward x: 64 -> 16 modes (per (c,k) of one batch) ----------------
__global__ void k_fx(int b) {
    __shared__ float2 sa[64][M2];
    __shared__ float2 tw[64][M2];
    int tid = threadIdx.x;  // 256
    int bc = b*CW + (blockIdx.x >> 3), k = blockIdx.x & 7;  // grid 256
    for (int t = tid; t < 512; t += 256)
        ((float4*)tw)[t] = ((const float4*)g_twF_)[t];
    const float2* src = g_b + (size_t)bc*64*M2*MD + k;
    for (int i = tid; i < 64*M2; i += 256) sa[i>>4][i&15] = src[(size_t)i*MD];
    __syncthreads();
    int i_ = tid >> 4, j = tid & 15;
    float re = 0.f, im = 0.f;
#pragma unroll
    for (int d = 0; d < 64; d++) {
        float2 a = sa[d][j], t = tw[d][i_];
        re += a.x*t.x - a.y*t.y;
        im += a.x*t.y + a.y*t.x;
    }
    g_ft[(((size_t)bc*M2 + i_)*M2 + j)*MD + k] = make_float2(re, im);
}

// ---------------- spectral channel mix: block per (i,j) of one batch ----------------
__global__ void k_spec(const float* __restrict__ spw, int layer, int b) {
    __shared__ float2 sa[CW][MD];        // 2 KB
    __shared__ float  red[8][CW][M2];    // 16 KB
    int tid = threadIdx.x;   // 256
    int blk = blockIdx.x;    // 256
    int i = blk >> 4, j = blk & 15;
    int corner = (i >= 8 ? 1 : 0) + (j >= 8 ? 2 : 0);
    int m1 = i & 7, m2 = j & 7;
    {
        int c = tid >> 3, k = tid & 7;
        sa[c][k] = g_ft[(((size_t)(b*CW+c)*M2 + i)*M2 + j)*MD + k];
    }
    __syncthreads();
    int o = tid & 31, cq = tid >> 5;   // cq 0..7
    const float* wbase = spw + ((size_t)(layer*4 + corner)*CW*CW*512
                               + (size_t)(m1*64 + m2*8)) * 2;
    float accr[MD], acci[MD];
#pragma unroll
    for (int k = 0; k < MD; k++) { accr[k] = 0.f; acci[k] = 0.f; }
#pragma unroll
    for (int c4 = 0; c4 < 4; c4++) {
        int c = cq*4 + c4;
        const float4* wv = (const float4*)(wbase + (size_t)(c*32 + o)*1024);
        float4 w0 = wv[0], w1 = wv[1], w2 = wv[2], w3 = wv[3];
        const float4* av = (const float4*)&sa[c][0];
        float4 a0 = av[0], a1 = av[1], a2 = av[2], a3 = av[3];
        accr[0] += a0.x*w0.x - a0.y*w0.y;  acci[0] += a0.x*w0.y + a0.y*w0.x;
        accr[1] += a0.z*w0.z - a0.w*w0.w;  acci[1] += a0.z*w0.w + a0.w*w0.z;
        accr[2] += a1.x*w1.x - a1.y*w1.y;  acci[2] += a1.x*w1.y + a1.y*w1.x;
        accr[3] += a1.z*w1.z - a1.w*w1.w;  acci[3] += a1.z*w1.w + a1.w*w1.z;
        accr[4] += a2.x*w2.x - a2.y*w2.y;  acci[4] += a2.x*w2.y + a2.y*w2.x;
        accr[5] += a2.z*w2.z - a2.w*w2.w;  acci[5] += a2.z*w2.w + a2.w*w2.z;
        accr[6] += a3.x*w3.x - a3.y*w3.y;  acci[6] += a3.x*w3.y + a3.y*w3.x;
        accr[7] += a3.z*w3.z - a3.w*w3.w;  acci[7] += a3.z*w3.w + a3.w*w3.z;
    }
#pragma unroll
    for (int k = 0; k < MD; k++) {
        red[cq][o][2*k]   = accr[k];
        red[cq][o][2*k+1] = acci[k];
    }
    __syncthreads();
    float* gs = (float*)g_sf;
#pragma unroll
    for (int r = 0; r < 2; r++) {
        int idx = r*256 + tid;          // 512 outputs
        int o2 = idx >> 4, v = idx & 15;
        float s = red[0][o2][v] + red[1][o2][v] + red[2][o2][v] + red[3][o2][v]
                + red[4][o2][v] + red[5][o2][v] + red[6][o2][v] + red[7][o2][v];
        gs[((((size_t)(b*CW+o2)*M2 + i)*M2 + j)*MD)*2 + v] = s;
    }
}

// ---------------- inverse x: 16 modes -> 64 (per (o,k) of one batch) ----------------
__global__ void k_ix(int b) {
    __shared__ float2 sa[M2][M2];
    __shared__ float2 tw[64][M2];
    int tid = threadIdx.x;  // 256
    int bo = b*CW + (blockIdx.x >> 3), k = blockIdx.x & 7;  // grid 256
    for (int t = tid; t < 512; t += 256)
        ((float4*)tw)[t] = ((const float4*)g_twI_)[t];
    const float2* src = g_sf + (size_t)bo*M2*M2*MD + k;
    for (int t = tid; t < M2*M2; t += 256) sa[t>>4][t&15] = src[(size_t)t*MD];
    __syncthreads();
    for (int t = tid; t < 64*M2; t += 256) {
        int d = t >> 4, j = t & 15;
        float re = 0.f, im = 0.f;
#pragma unroll
        for (int ii = 0; ii < M2; ii++) {
            float2 a = sa[ii][j], w = tw[d][ii];
            re += a.x*w.x - a.y*w.y;
            im += a.x*w.y + a.y*w.x;
        }
        g_b[(((size_t)bo*64 + d)*M2 + j)*MD + k] = make_float2(re, im);
    }
}

// ---------------- inverse y: 16 modes -> 64 (k-pair f32x2, per (o,d)) ----------------
__global__ void __launch_bounds__(256) k_iy(int b) {
    __shared__ float2 sa[M2][MD];       // 2 KB
    __shared__ float4 tw4[64][M2];      // 16 KB packed (c,s,-s,c)
    int tid = threadIdx.x;  // 256
    int bod = b*CW*RR + blockIdx.x;     // grid 2048
    for (int t = tid; t < 1024; t += 256) ((float4*)tw4)[t] = g_tw4I[t];
    const float2* src = g_b + (size_t)bod*M2*MD;
    if (tid < M2*MD) ((float2*)sa)[tid] = src[tid];
    __syncthreads();
    int h = tid >> 2, kp = tid & 3;
    u64t acc0 = 0ull, acc1 = 0ull;
#pragma unroll
    for (int j = 0; j < M2; j++) {
        float4 a = *(const float4*)&sa[j][kp*2];
        float4 t4 = tw4[h][j];
        u64t tlo = *(const u64t*)&t4.x;   // (c, s)
        u64t thi = *(const u64t*)&t4.z;   // (-s, c)
        fma2(acc0, dup2(a.x), tlo); fma2(acc0, dup2(a.y), thi);
        fma2(acc1, dup2(a.z), tlo); fma2(acc1, dup2(a.w), thi);
    }
    float re0, im0, re1, im1;
    up2(acc0, re0, im0); up2(acc1, re1, im1);
    *(float4*)&g_a[((size_t)bod*64 + h)*MD + kp*2] = make_float4(re0, im0, re1, im1);
}

// ---------------- layer update: HMMA pointwise + irfft-z + gelu + fwd-z ----------------
__global__ void __launch_bounds__(256) k_layer(const float* __restrict__ wpw,
                        const float* __restrict__ bpw,
                        int layer, int do_gelu, int flip, int do_fz, int b) {
    __shared__ unsigned short sxh[CW][136];     // x in [c][pt]; out reused as [o][pt]
    __shared__ unsigned short w1h[CW][36];      // pointwise W transposed [o][c] fp16
    __shared__ float szr[2][MD][CW];            // [q][k][o] 2 KB
    __shared__ float szi[2][MD][CW];            // 2 KB
    __shared__ float crt[MD][64], cit[MD][64];  // 4 KB
    __shared__ float2 twf[64][MD];              // 4 KB
    __shared__ float sbf[CW];
    const __half* __restrict__ xin  = flip ? g_x1 : g_x0;
    __half* __restrict__       xout = flip ? g_x0 : g_x1;
    int tid = threadIdx.x;  // 256
    int dh0 = blockIdx.x*2; // grid 2048
    for (int t = tid; t < 512; t += 256) {
        ((float*)crt)[t] = g_crt_[t];
        ((float*)cit)[t] = g_cit_[t];
        ((float2*)twf)[t] = g_twf_[t];
    }
    for (int t = tid; t < 1024; t += 256) {
        int o = t >> 5, c = t & 31;
        __half hv = __float2half_rn(wpw[layer*1024 + c*32 + o]);
        w1h[o][c] = *(unsigned short*)&hv;
    }
    if (tid < CW) sbf[tid] = bpw[layer*CW + tid];
    // x load: row c = 128 halfs = 16 uint4 (uint4 = 8 halfs)
    for (int t = tid; t < 512; t += 256) {
        int c = t >> 4, r = t & 15;
        *(uint4*)&sxh[c][r*8] =
            *(const uint4*)&xin[((size_t)(b*CW+c)*4096 + dh0)*64 + r*8];
    }
    // z modes [q][k][o]
    for (int t = tid; t < 512; t += 256) {
        int o = t >> 4, q = (t >> 3) & 1, k = t & 7;
        float2 z = g_a[((size_t)(b*CW+o)*4096 + dh0+q)*MD + k];
        szr[q][k][o] = z.x; szi[q][k][o] = z.y;
    }
    __syncthreads();
    int wid = tid >> 5, lane = tid & 31;
    int g = lane >> 2, t4 = lane & 3;
    int plo = wid*16 + g, phi = plo + 8;
    int q = wid >> 2;
    int wwlo = plo & 63, wwhi = phi & 63;
    u32t afr[2][4];
#pragma unroll
    for (int s = 0; s < 2; s++) {
        int c0 = s*16 + 2*t4;
        afr[s][0] = (u32t)sxh[c0][plo]   | ((u32t)sxh[c0+1][plo] << 16);
        afr[s][1] = (u32t)sxh[c0][phi]   | ((u32t)sxh[c0+1][phi] << 16);
        afr[s][2] = (u32t)sxh[c0+8][plo] | ((u32t)sxh[c0+9][plo] << 16);
        afr[s][3] = (u32t)sxh[c0+8][phi] | ((u32t)sxh[c0+9][phi] << 16);
    }
    float cf[4][4];
#pragma unroll
    for (int nt = 0; nt < 4; nt++) {
        float bv0 = sbf[nt*8 + 2*t4], bv1 = sbf[nt*8 + 2*t4 + 1];
        cf[nt][0] = bv0; cf[nt][1] = bv1; cf[nt][2] = bv0; cf[nt][3] = bv1;
    }
#pragma unroll
    for (int nt = 0; nt < 4; nt++) {
        int n = nt*8 + g;
        u32t b00 = *(const u32t*)&w1h[n][2*t4];
        u32t b01 = *(const u32t*)&w1h[n][2*t4 + 8];
        mma16816(cf[nt], afr[0][0], afr[0][1], afr[0][2], afr[0][3], b00, b01);
        u32t b10 = *(const u32t*)&w1h[n][2*t4 + 16];
        u32t b11 = *(const u32t*)&w1h[n][2*t4 + 24];
        mma16816(cf[nt], afr[1][0], afr[1][1], afr[1][2], afr[1][3], b10, b11);
    }
    u64t lo[4], hi[4];
#pragma unroll
    for (int nt = 0; nt < 4; nt++) {
        lo[nt] = pk2(cf[nt][0], cf[nt][1]);
        hi[nt] = pk2(cf[nt][2], cf[nt][3]);
    }
#pragma unroll
    for (int k = 0; k < MD; k++) {
        u64t crl = dup2(crt[k][wwlo]), cil = dup2(cit[k][wwlo]);
        u64t crh = dup2(crt[k][wwhi]), cih = dup2(cit[k][wwhi]);
#pragma unroll
        for (int nt = 0; nt < 4; nt++) {
            int o0 = nt*8 + 2*t4;
            u64t zr = *(const u64t*)&szr[q][k][o0];
            u64t zi = *(const u64t*)&szi[q][k][o0];
            fma2(lo[nt], zr, crl); fma2(lo[nt], zi, cil);
            fma2(hi[nt], zr, crh); fma2(hi[nt], zi, cih);
        }
    }
#pragma unroll
    for (int nt = 0; nt < 4; nt++) {
        int o0 = nt*8 + 2*t4;
        float v0, v1, v2, v3;
        up2(lo[nt], v0, v1);
        up2(hi[nt], v2, v3);
        if (do_gelu) {
            v0 = gelu_fast(v0); v1 = gelu_fast(v1);
            v2 = gelu_fast(v2); v3 = gelu_fast(v3);
        }
        __half h0 = __float2half_rn(v0), h1 = __float2half_rn(v1);
        __half h2 = __float2half_rn(v2), h3 = __float2half_rn(v3);
        sxh[o0  ][plo] = *(unsigned short*)&h0;
        sxh[o0+1][plo] = *(unsigned short*)&h1;
        sxh[o0  ][phi] = *(unsigned short*)&h2;
        sxh[o0+1][phi] = *(unsigned short*)&h3;
    }
    __syncthreads();
    for (int t = tid; t < 512; t += 256) {
        int o = t >> 4, r = t & 15;
        *(uint4*)&xout[((size_t)(b*CW+o)*4096 + dh0)*64 + r*8] =
            *(const uint4*)&sxh[o][r*8];
    }
    if (do_fz) {
        int o = tid >> 3, k = tid & 7;
#pragma unroll
        for (int q2 = 0; q2 < 2; q2++) {
            u64t zacc = 0ull;
#pragma unroll
            for (int wp = 0; wp < 32; wp++) {
                __half2 h2 = *(const __half2*)&sxh[o][q2*64 + wp*2];
                float2 f = __half22float2(h2);
                fma2(zacc, dup2(f.x), *(const u64t*)&twf[wp*2][k]);
                fma2(zacc, dup2(f.y), *(const u64t*)&twf[wp*2+1][k]);
            }
            float re, im; up2(zacc, re, im);
            g_a[((size_t)(b*CW+o)*4096 + dh0+q2)*MD + k] = make_float2(re, im);
        }
    }
}

// ---------------- fc head via HMMA: fc1(mma) -> gelu -> fc2(scalar) -> tau + stencil ----------------
__global__ void __launch_bounds__(256) k_fc_mma(const float* __restrict__ w1,
                     const float* __restrict__ b1, const float* __restrict__ w2,
                     const float* __restrict__ b2, const float* __restrict__ u,
                     float* __restrict__ tau, float* __restrict__ out, int b) {
    __shared__ unsigned short sx[CW][136];
    __shared__ unsigned short sw1p[FCHN][36];
    __shared__ float w2f[FCHN][6];
    __shared__ float sb1f[FCHN];
    int tid = threadIdx.x;   // 256
    int s0 = blockIdx.x*128; // grid 2048
    for (int t = tid; t < 512; t += 256) {
        int c = t >> 4, r = t & 15;
        *(uint4*)&sx[c][r*8] =
            *(const uint4*)&g_x0[(((size_t)b*CW + c) << 18) + s0 + r*8];
    }
    for (int t = tid; t < CW*FCHN; t += 256) {
        int c = t >> 7, h = t & 127;
        __half hv = __float2half_rn(w1[c*FCHN + h]);
        sw1p[h][c] = *(unsigned short*)&hv;
    }
    for (int t = tid; t < FCHN*6; t += 256) w2f[t/6][t%6] = w2[t];
    if (tid < FCHN) sb1f[tid] = b1[tid];
    __shared__ float sb2f[6];
    if (tid < 6) sb2f[tid] = b2[tid];
    __syncthreads();

    int wid = tid >> 5, lane = tid & 31;
    int g = lane >> 2, t4 = lane & 3;
    int plo = wid*16 + g, phi = plo + 8;
    u32t afr[2][4];
#pragma unroll
    for (int s = 0; s < 2; s++) {
        int c0 = s*16 + 2*t4;
        afr[s][0] = (u32t)sx[c0][plo]   | ((u32t)sx[c0+1][plo] << 16);
        afr[s][1] = (u32t)sx[c0][phi]   | ((u32t)sx[c0+1][phi] << 16);
        afr[s][2] = (u32t)sx[c0+8][plo] | ((u32t)sx[c0+9][plo] << 16);
        afr[s][3] = (u32t)sx[c0+8][phi] | ((u32t)sx[c0+9][phi] << 16);
    }
    float cf[16][4];
#pragma unroll
    for (int t = 0; t < 16; t++) {
        float bv0 = sb1f[t*8 + 2*t4], bv1 = sb1f[t*8 + 2*t4 + 1];
        cf[t][0] = bv0; cf[t][1] = bv1; cf[t][2] = bv0; cf[t][3] = bv1;
    }
#pragma unroll
    for (int t = 0; t < 16; t++) {
        int n = t*8 + g;
        u32t b00 = *(const u32t*)&sw1p[n][2*t4];
        u32t b01 = *(const u32t*)&sw1p[n][2*t4 + 8];
        mma16816(cf[t], afr[0][0], afr[0][1], afr[0][2], afr[0][3], b00, b01);
        u32t b10 = *(const u32t*)&sw1p[n][2*t4 + 16];
        u32t b11 = *(const u32t*)&sw1p[n][2*t4 + 24];
        mma16816(cf[t], afr[1][0], afr[1][1], afr[1][2], afr[1][3], b10, b11);
    }
    float part[6][2];
#pragma unroll
    for (int o = 0; o < 6; o++) { part[o][0] = sb2f[o]*0.25f; part[o][1] = sb2f[o]*0.25f; }
#pragma unroll
    for (int t = 0; t < 16; t++) {
        int h0 = t*8 + 2*t4, h1 = h0 + 1;
        float d0 = gelu_fast(cf[t][0]);
        float d1 = gelu_fast(cf[t][1]);
        float d2 = gelu_fast(cf[t][2]);
        float d3 = gelu_fast(cf[t][3]);
#pragma unroll
        for (int o = 0; o < 6; o++) {
            float wa = w2f[h0][o], wb = w2f[h1][o];
            part[o][0] += d0*wa + d1*wb;
            part[o][1] += d2*wa + d3*wb;
        }
    }
    float sums[6][2];
#pragma unroll
    for (int o = 0; o < 6; o++) {
#pragma unroll
        for (int r = 0; r < 2; r++) {
            float v = part[o][r];
            v += __shfl_xor_sync(0xffffffffu, v, 1);
            v += __shfl_xor_sync(0xffffffffu, v, 2);
            sums[o][r] = v;
        }
    }
    int sl = s0 + plo, sh = s0 + phi;
    if (t4 < 3) {
#pragma unroll
        for (int r = 0; r < 2; r++) {
            int sp = r ? sh : sl;
            tau[(((size_t)b*6 + t4)     << 18) + sp] = sums[t4][r];
            tau[(((size_t)b*6 + t4 + 3) << 18) + sp] = sums[t4+3][r];
        }
        int i = t4;
        const float dx = 2.0f*3.14159265358979323846f/64.0f;
        const float inv2dx = 1.0f/(2.0f*dx);
        const float invdx2 = 1.0f/(dx*dx);
        const float* ub = u + ((size_t)b*3 << 18);
#pragma unroll
        for (int r = 0; r < 2; r++) {
            int sp = r ? sh : sl;
            int d = sp >> 12, h = (sp >> 6) & 63, w = sp & 63;
            int dp = (((d+1)&63)<<12) | (h<<6) | w;
            int dm = (((d+63)&63)<<12) | (h<<6) | w;
            int hp = (d<<12) | (((h+1)&63)<<6) | w;
            int hm = (d<<12) | (((h+63)&63)<<6) | w;
            int wp = (d<<12) | (h<<6) | ((w+1)&63);
            int wm = (d<<12) | (h<<6) | ((w+63)&63);
            float u0 = ub[(0<<18)+sp], u1 = ub[(1<<18)+sp], u2 = ub[(2<<18)+sp];
            const float* ui = ub + (i<<18);
            float xp = ui[dp], xm = ui[dm];
            float yp = ui[hp], ym = ui[hm];
            float zp = ui[wp], zm = ui[wm];
            float uc = (i == 0) ? u0 : (i == 1) ? u1 : u2;
            float conv = -( u0*(xp-xm) + u1*(yp-ym) + u2*(zp-zm) )*inv2dx;
            float lap  = (xp+xm+yp+ym+zp+zm - 6.f*uc)*invdx2;
            out[((size_t)(b*3+i)<<18) + sp] = conv + 0.000185f*lap + 0.001f*sums[i][r];
        }
    }
}

extern "C" void kernel_launch(void* const* d_in, const int* in_sizes, int n_in,
                              void* d_out, int out_size) {
    (void)in_sizes; (void)n_in; (void)out_size;
    const float* u      = (const float*)d_in[0];
    const float* fc0_w  = (const float*)d_in[1];
    const float* fc0_b  = (const float*)d_in[2];
    const float* spec_w = (const float*)d_in[3];
    const float* w_pw   = (const float*)d_in[4];
    const float* b_pw   = (const float*)d_in[5];
    const float* fc1_w  = (const float*)d_in[6];
    const float* fc1_b  = (const float*)d_in[7];
    const float* fc2_w  = (const float*)d_in[8];
    const float* fc2_b  = (const float*)d_in[9];
    float* out = (float*)d_out;
    float* tau = out + (size_t)BN*3*SP;   // du_dt first, then tau

    cudaStream_t st[BN];
    cudaEvent_t  evR, evD[BN];
    for (int i = 0; i < BN; i++)
        cudaStreamCreateWithFlags(&st[i], cudaStreamNonBlocking);
    cudaEventCreateWithFlags(&evR, cudaEventDisableTiming);
    for (int i = 0; i < BN; i++)
        cudaEventCreateWithFlags(&evD[i], cudaEventDisableTiming);

    k_init<<<4, 256>>>();
    cudaEventRecord(evR, 0);

    for (int b = 0; b < BN; b++) {
        cudaStreamWaitEvent(st[b], evR, 0);
        k_fc0<<<RR*RR, 256, 0, st[b]>>>(u, fc0_w, fc0_b, b);
        for (int l = 0; l < NLY; l++) {
            int flip = l & 1;  // input buffer: 0 -> g_x0, 1 -> g_x1
            k_fy  <<<CW*RR/2, 128, 0, st[b]>>>(b);
            k_fx  <<<CW*MD,   256, 0, st[b]>>>(b);
            k_spec<<<M2*M2,   256, 0, st[b]>>>(spec_w, l, b);
            k_ix  <<<CW*MD,   256, 0, st[b]>>>(b);
            k_iy  <<<CW*RR,   256, 0, st[b]>>>(b);
            k_layer<<<RR*RR/2, 256, 0, st[b]>>>(w_pw, b_pw, l,
                                                (l < NLY-1) ? 1 : 0, flip,
                                                (l < NLY-1) ? 1 : 0, b);
        }
        k_fc_mma<<<SP/128, 256, 0, st[b]>>>(fc1_w, fc1_b, fc2_w, fc2_b, u, tau, out, b);
        cudaEventRecord(evD[b], st[b]);
        cudaStreamWaitEvent(0, evD[b], 0);
    }

    for (int i = 0; i < BN; i++) cudaStreamDestroy(st[i]);
    cudaEventDestroy(evR);
    for (int i = 0; i < BN; i++) cudaEventDestroy(evD[i]);
}

// round 16
// speedup vs baseline: 1.1387x; 1.1387x over previous
#include <cuda_runtime.h>
#include <cuda_fp16.h>
#include <math.h>

#define BN 4
#define CW 32
#define RR 64
#define SP (RR*RR*RR)        // 262144
#define MD 8
#define M2 16
#define NLY 4
#define FCHN 128
#define PI2_64 0.09817477042468103f   // 2*pi/64

typedef unsigned long long u64t;
typedef unsigned int u32t;

__device__ __forceinline__ u64t pk2(float lo, float hi) {
    u64t r; asm("mov.b64 %0, {%1,%2};" : "=l"(r) : "f"(lo), "f"(hi)); return r;
}
__device__ __forceinline__ u64t dup2(float v) { return pk2(v, v); }
__device__ __forceinline__ void up2(u64t v, float& a, float& b) {
    asm("mov.b64 {%0,%1}, %2;" : "=f"(a), "=f"(b) : "l"(v));
}
__device__ __forceinline__ void fma2(u64t& d, u64t a, u64t b) {
    asm("fma.rn.f32x2 %0, %1, %2, %0;" : "+l"(d) : "l"(a), "l"(b));
}

// ---------------- scratch (static device memory; no allocation) ----------------
__device__ __half  g_x0[BN*CW*SP];              // 67 MB (fp16 activations)
__device__ __half  g_x1[BN*CW*SP];              // 67 MB
__device__ float2 g_a [BN*CW*RR*RR*MD];         // 33.5 MB
__device__ float2 g_b [BN*CW*RR*M2*MD];         // 8.4 MB
__device__ float2 g_ft[BN*CW*M2*M2*MD];         // 2 MB
__device__ float2 g_sf[BN*CW*M2*M2*MD];         // 2 MB

// precomputed twiddle tables
__device__ float2 g_twf_[64*MD];    // fwd z: (c,-s)  [ww][k]
__device__ float  g_crt_[MD*64];    // irfft z coef   [k][ww]
__device__ float  g_cit_[MD*64];
__device__ float2 g_twF_[64*M2];    // fwd y/x: (c,-s) [h][j], ky = j<8?j:j+48
__device__ float2 g_twI_[64*M2];    // inv y/x: (c, s)

__global__ void k_init() {
    int t = blockIdx.x*blockDim.x + threadIdx.x;
    if (t < 512) {
        int ww = t >> 3, k = t & 7;
        float s, c; sincosf(((ww*k)&63)*PI2_64, &s, &c);
        g_twf_[t] = make_float2(c, -s);
        const float scale = 1.0f/262144.0f;
        g_crt_[k*64+ww] = (k == 0) ? scale : 2.f*scale*c;
        g_cit_[k*64+ww] = (k == 0) ? 0.f   : -2.f*scale*s;
    }
    if (t < 1024) {
        int h = t >> 4, j = t & 15;
        int ky = (j < 8) ? j : j + 48;
        float s, c; sincosf(((ky*h)&63)*PI2_64, &s, &c);
        g_twF_[t] = make_float2(c, -s);
        g_twI_[t] = make_float2(c,  s);
    }
}

__device__ __forceinline__ float gelu_fast(float a) {
    float z = 1.5957691216057308f * (a + 0.044715f*a*a*a);
    float e;
    asm("ex2.approx.f32 %0, %1;" : "=f"(e) : "f"(-1.4426950408889634f*z));
    float r;
    asm("rcp.approx.f32 %0, %1;" : "=f"(r) : "f"(1.0f + e));
    return a * r;
}

__device__ __forceinline__ void mma16816(float* d, u32t a0, u32t a1, u32t a2, u32t a3,
                                         u32t b0, u32t b1) {
    asm volatile(
        "mma.sync.aligned.m16n8k16.row.col.f32.f16.f16.f32 "
        "{%0,%1,%2,%3}, {%4,%5,%6,%7}, {%8,%9}, {%0,%1,%2,%3};"
        : "+f"(d[0]), "+f"(d[1]), "+f"(d[2]), "+f"(d[3])
        : "r"(a0), "r"(a1), "r"(a2), "r"(a3), "r"(b0), "r"(b1));
}

// ---------------- fc0 + fused forward-z DFT (per batch) ----------------
__global__ void k_fc0(const float* __restrict__ u, const float* __restrict__ w,
                      const float* __restrict__ bias, int b) {
    __shared__ float  su[3][64];
    __shared__ float  sw[3*CW], sb[CW];
    __shared__ float  sxo[CW][65];
    __shared__ float2 twf[64][MD];
    int tid = threadIdx.x;  // 256
    int dh = blockIdx.x;    // 4096
    for (int t = tid; t < 512; t += 256) ((float2*)twf)[t] = g_twf_[t];
    if (tid < 3*CW) sw[tid] = w[tid];
    if (tid < CW)   sb[tid] = bias[tid];
    if (tid < 192) {
        int j = tid >> 6, ww = tid & 63;
        su[j][ww] = u[((size_t)(b*3+j) << 18) + dh*64 + ww];
    }
    __syncthreads();
    {
        int ww = tid & 63, o0 = (tid >> 6)*8;
#pragma unroll
        for (int oi = 0; oi < 8; oi++) {
            int o = o0 + oi;
            float acc = sb[o] + su[0][ww]*sw[o] + su[1][ww]*sw[CW+o] + su[2][ww]*sw[2*CW+o];
            sxo[o][ww] = acc;
            g_x0[((size_t)(b*CW+o) << 18) + dh*64 + ww] = __float2half_rn(acc);
        }
    }
    __syncthreads();
    {
        int o = tid >> 3, k = tid & 7;
        u64t zacc = 0ull;
#pragma unroll
        for (int ww = 0; ww < 64; ww++)
            fma2(zacc, dup2(sxo[o][ww]), *(const u64t*)&twf[ww][k]);
        float re, im; up2(zacc, re, im);
        g_a[((size_t)((b*CW+o)*4096 + dh))*MD + k] = make_float2(re, im);
    }
}

// ---------------- forward y: 64 -> 16 modes (per (c,d) of one batch) ----------------
__global__ void k_fy(int b) {
    __shared__ float2 sa[64][MD];
    __shared__ float2 tw[64][M2];
    int tid = threadIdx.x;  // 128
    int bcd = b*CW*RR + blockIdx.x;   // grid 2048
    for (int t = tid; t < 512; t += 128)
        ((float4*)tw)[t] = ((const float4*)g_twF_)[t];
    const float2* src = g_a + (size_t)bcd*64*MD;
    for (int i = tid; i < 64*MD; i += 128) sa[i>>3][i&7] = src[i];
    __syncthreads();
    int j = tid >> 3, k = tid & 7;
    float re = 0.f, im = 0.f;
#pragma unroll
    for (int h = 0; h < 64; h++) {
        float2 a = sa[h][k], t = tw[h][j];
        re += a.x*t.x - a.y*t.y;
        im += a.x*t.y + a.y*t.x;
    }
    g_b[((size_t)bcd*M2 + j)*MD + k] = make_float2(re, im);
}

// ---------------- forward x: 64 -> 16 modes (per (c,k) of one batch) ----------------
__global__ void k_fx(int b) {
    __shared__ float2 sa[64][M2];
    __shared__ float2 tw[64][M2];
    int tid = threadIdx.x;  // 256
    int bc = b*CW + (blockIdx.x >> 3), k = blockIdx.x & 7;  // grid 256
    for (int t = tid; t < 512; t += 256)
        ((float4*)tw)[t] = ((const float4*)g_twF_)[t];
    const float2* src = g_b + (size_t)bc*64*M2*MD + k;
    for (int i = tid; i < 64*M2; i += 256) sa[i>>4][i&15] = src[(size_t)i*MD];
    __syncthreads();
    int i_ = tid >> 4, j = tid & 15;
    float re = 0.f, im = 0.f;
#pragma unroll
    for (int d = 0; d < 64; d++) {
        float2 a = sa[d][j], t = tw[d][i_];
        re += a.x*t.x - a.y*t.y;
        im += a.x*t.y + a.y*t.x;
    }
    g_ft[(((size_t)bc*M2 + i_)*M2 + j)*MD + k] = make_float2(re, im);
}

// ---------------- spectral channel mix: block per (i,j) of one batch ----------------
__global__ void k_spec(const float* __restrict__ spw, int layer, int b) {
    __shared__ float2 sa[CW][MD];        // 2 KB
    __shared__ float  red[8][CW][M2];    // 16 KB
    int tid = threadIdx.x;   // 256
    int blk = blockIdx.x;    // 256
    int i = blk >> 4, j = blk & 15;
    int corner = (i >= 8 ? 1 : 0) + (j >= 8 ? 2 : 0);
    int m1 = i & 7, m2 = j & 7;
    {
        int c = tid >> 3, k = tid & 7;
        sa[c][k] = g_ft[(((size_t)(b*CW+c)*M2 + i)*M2 + j)*MD + k];
    }
    __syncthreads();
    int o = tid & 31, cq = tid >> 5;   // cq 0..7
    const float* wbase = spw + ((size_t)(layer*4 + corner)*CW*CW*512
                               + (size_t)(m1*64 + m2*8)) * 2;
    float accr[MD], acci[MD];
#pragma unroll
    for (int k = 0; k < MD; k++) { accr[k] = 0.f; acci[k] = 0.f; }
#pragma unroll
    for (int c4 = 0; c4 < 4; c4++) {
        int c = cq*4 + c4;
        const float4* wv = (const float4*)(wbase + (size_t)(c*32 + o)*1024);
        float4 w0 = wv[0], w1 = wv[1], w2 = wv[2], w3 = wv[3];
        const float4* av = (const float4*)&sa[c][0];
        float4 a0 = av[0], a1 = av[1], a2 = av[2], a3 = av[3];
        accr[0] += a0.x*w0.x - a0.y*w0.y;  acci[0] += a0.x*w0.y + a0.y*w0.x;
        accr[1] += a0.z*w0.z - a0.w*w0.w;  acci[1] += a0.z*w0.w + a0.w*w0.z;
        accr[2] += a1.x*w1.x - a1.y*w1.y;  acci[2] += a1.x*w1.y + a1.y*w1.x;
        accr[3] += a1.z*w1.z - a1.w*w1.w;  acci[3] += a1.z*w1.w + a1.w*w1.z;
        accr[4] += a2.x*w2.x - a2.y*w2.y;  acci[4] += a2.x*w2.y + a2.y*w2.x;
        accr[5] += a2.z*w2.z - a2.w*w2.w;  acci[5] += a2.z*w2.w + a2.w*w2.z;
        accr[6] += a3.x*w3.x - a3.y*w3.y;  acci[6] += a3.x*w3.y + a3.y*w3.x;
        accr[7] += a3.z*w3.z - a3.w*w3.w;  acci[7] += a3.z*w3.w + a3.w*w3.z;
    }
#pragma unroll
    for (int k = 0; k < MD; k++) {
        red[cq][o][2*k]   = accr[k];
        red[cq][o][2*k+1] = acci[k];
    }
    __syncthreads();
    float* gs = (float*)g_sf;
#pragma unroll
    for (int r = 0; r < 2; r++) {
        int idx = r*256 + tid;          // 512 outputs
        int o2 = idx >> 4, v = idx & 15;
        float s = red[0][o2][v] + red[1][o2][v] + red[2][o2][v] + red[3][o2][v]
                + red[4][o2][v] + red[5][o2][v] + red[6][o2][v] + red[7][o2][v];
        gs[((((size_t)(b*CW+o2)*M2 + i)*M2 + j)*MD)*2 + v] = s;
    }
}

// ---------------- inverse x: 16 modes -> 64 (per (o,k) of one batch) ----------------
__global__ void k_ix(int b) {
    __shared__ float2 sa[M2][M2];
    __shared__ float2 tw[64][M2];
    int tid = threadIdx.x;  // 256
    int bo = b*CW + (blockIdx.x >> 3), k = blockIdx.x & 7;  // grid 256
    for (int t = tid; t < 512; t += 256)
        ((float4*)tw)[t] = ((const float4*)g_twI_)[t];
    const float2* src = g_sf + (size_t)bo*M2*M2*MD + k;
    for (int t = tid; t < M2*M2; t += 256) sa[t>>4][t&15] = src[(size_t)t*MD];
    __syncthreads();
    for (int t = tid; t < 64*M2; t += 256) {
        int d = t >> 4, j = t & 15;
        float re = 0.f, im = 0.f;
#pragma unroll
        for (int ii = 0; ii < M2; ii++) {
            float2 a = sa[ii][j], w = tw[d][ii];
            re += a.x*w.x - a.y*w.y;
            im += a.x*w.y + a.y*w.x;
        }
        g_b[(((size_t)bo*64 + d)*M2 + j)*MD + k] = make_float2(re, im);
    }
}

// ---------------- inverse y: 16 modes -> 64 (per (o,d) of one batch) ----------------
__global__ void k_iy(int b) {
    __shared__ float2 sa[M2][MD];
    __shared__ float2 tw[64][M2];
    int tid = threadIdx.x;  // 128
    int bod = b*CW*RR + blockIdx.x;   // grid 2048
    for (int t = tid; t < 512; t += 128)
        ((float4*)tw)[t] = ((const float4*)g_twI_)[t];
    const float2* src = g_b + (size_t)bod*M2*MD;
    for (int t = tid; t < M2*MD; t += 128) sa[t>>3][t&7] = src[t];
    __syncthreads();
    for (int t = tid; t < 64*MD; t += 128) {
        int h = t >> 3, k = t & 7;
        float re = 0.f, im = 0.f;
#pragma unroll
        for (int j = 0; j < M2; j++) {
            float2 a = sa[j][k], w = tw[h][j];
            re += a.x*w.x - a.y*w.y;
            im += a.x*w.y + a.y*w.x;
        }
        g_a[((size_t)bod*64 + h)*MD + k] = make_float2(re, im);
    }
}

// ---------------- layer update: HMMA pointwise + irfft-z + gelu + fwd-z ----------------
__global__ void __launch_bounds__(256) k_layer(const float* __restrict__ wpw,
                        const float* __restrict__ bpw,
                        int layer, int do_gelu, int flip, int do_fz, int b) {
    __shared__ unsigned short sxh[CW][136];     // x in [c][pt]; out reused as [o][pt]
    __shared__ unsigned short w1h[CW][36];      // pointwise W transposed [o][c] fp16
    __shared__ float szr[2][MD][CW];            // [q][k][o] 2 KB
    __shared__ float szi[2][MD][CW];            // 2 KB
    __shared__ float crt[MD][64], cit[MD][64];  // 4 KB
    __shared__ float2 twf[64][MD];              // 4 KB
    __shared__ float sbf[CW];
    const __half* __restrict__ xin  = flip ? g_x1 : g_x0;
    __half* __restrict__       xout = flip ? g_x0 : g_x1;
    int tid = threadIdx.x;  // 256
    int dh0 = blockIdx.x*2; // grid 2048
    for (int t = tid; t < 512; t += 256) {
        ((float*)crt)[t] = g_crt_[t];
        ((float*)cit)[t] = g_cit_[t];
        ((float2*)twf)[t] = g_twf_[t];
    }
    for (int t = tid; t < 1024; t += 256) {
        int o = t >> 5, c = t & 31;
        __half hv = __float2half_rn(wpw[layer*1024 + c*32 + o]);
        w1h[o][c] = *(unsigned short*)&hv;
    }
    if (tid < CW) sbf[tid] = bpw[layer*CW + tid];
    // x load: row c = 128 halfs = 16 uint4 (uint4 = 8 halfs); 32*16 = 512 over 256 thr
    for (int t = tid; t < 512; t += 256) {
        int c = t >> 4, r = t & 15;
        *(uint4*)&sxh[c][r*8] =
            *(const uint4*)&xin[((size_t)(b*CW+c)*4096 + dh0)*64 + r*8];
    }
    // z modes [q][k][o]
    for (int t = tid; t < 512; t += 256) {
        int o = t >> 4, q = (t >> 3) & 1, k = t & 7;
        float2 z = g_a[((size_t)(b*CW+o)*4096 + dh0+q)*MD + k];
        szr[q][k][o] = z.x; szi[q][k][o] = z.y;
    }
    __syncthreads();
    int wid = tid >> 5, lane = tid & 31;
    int g = lane >> 2, t4 = lane & 3;
    int plo = wid*16 + g, phi = plo + 8;
    int q = wid >> 2;                     // z-line index of this warp's points
    int wwlo = plo & 63, wwhi = phi & 63;
    // A fragments (validated mapping from k_fc_mma)
    u32t afr[2][4];
#pragma unroll
    for (int s = 0; s < 2; s++) {
        int c0 = s*16 + 2*t4;
        afr[s][0] = (u32t)sxh[c0][plo]   | ((u32t)sxh[c0+1][plo] << 16);
        afr[s][1] = (u32t)sxh[c0][phi]   | ((u32t)sxh[c0+1][phi] << 16);
        afr[s][2] = (u32t)sxh[c0+8][plo] | ((u32t)sxh[c0+9][plo] << 16);
        afr[s][3] = (u32t)sxh[c0+8][phi] | ((u32t)sxh[c0+9][phi] << 16);
    }
    float cf[4][4];
#pragma unroll
    for (int nt = 0; nt < 4; nt++) {
        float bv0 = sbf[nt*8 + 2*t4], bv1 = sbf[nt*8 + 2*t4 + 1];
        cf[nt][0] = bv0; cf[nt][1] = bv1; cf[nt][2] = bv0; cf[nt][3] = bv1;
    }
#pragma unroll
    for (int nt = 0; nt < 4; nt++) {
        int n = nt*8 + g;
        u32t b00 = *(const u32t*)&w1h[n][2*t4];
        u32t b01 = *(const u32t*)&w1h[n][2*t4 + 8];
        mma16816(cf[nt], afr[0][0], afr[0][1], afr[0][2], afr[0][3], b00, b01);
        u32t b10 = *(const u32t*)&w1h[n][2*t4 + 16];
        u32t b11 = *(const u32t*)&w1h[n][2*t4 + 24];
        mma16816(cf[nt], afr[1][0], afr[1][1], afr[1][2], afr[1][3], b10, b11);
    }
    // irfft-z contribution on frags (f32x2, lo = row plo, hi = row phi)
    u64t lo[4], hi[4];
#pragma unroll
    for (int nt = 0; nt < 4; nt++) {
        lo[nt] = pk2(cf[nt][0], cf[nt][1]);
        hi[nt] = pk2(cf[nt][2], cf[nt][3]);
    }
#pragma unroll
    for (int k = 0; k < MD; k++) {
        u64t crl = dup2(crt[k][wwlo]), cil = dup2(cit[k][wwlo]);
        u64t crh = dup2(crt[k][wwhi]), cih = dup2(cit[k][wwhi]);
#pragma unroll
        for (int nt = 0; nt < 4; nt++) {
            int o0 = nt*8 + 2*t4;
            u64t zr = *(const u64t*)&szr[q][k][o0];
            u64t zi = *(const u64t*)&szi[q][k][o0];
            fma2(lo[nt], zr, crl); fma2(lo[nt], zi, cil);
            fma2(hi[nt], zr, crh); fma2(hi[nt], zi, cih);
        }
    }
    // gelu + write fp16 outputs into sxh[o][pt] (columns are warp-private)
#pragma unroll
    for (int nt = 0; nt < 4; nt++) {
        int o0 = nt*8 + 2*t4;
        float v0, v1, v2, v3;
        up2(lo[nt], v0, v1);
        up2(hi[nt], v2, v3);
        if (do_gelu) {
            v0 = gelu_fast(v0); v1 = gelu_fast(v1);
            v2 = gelu_fast(v2); v3 = gelu_fast(v3);
        }
        __half h0 = __float2half_rn(v0), h1 = __float2half_rn(v1);
        __half h2 = __float2half_rn(v2), h3 = __float2half_rn(v3);
        sxh[o0  ][plo] = *(unsigned short*)&h0;
        sxh[o0+1][plo] = *(unsigned short*)&h1;
        sxh[o0  ][phi] = *(unsigned short*)&h2;
        sxh[o0+1][phi] = *(unsigned short*)&h3;
    }
    __syncthreads();
    // cooperative global store: row o = 128 halfs = 16 uint4
    for (int t = tid; t < 512; t += 256) {
        int o = t >> 4, r = t & 15;
        *(uint4*)&xout[((size_t)(b*CW+o)*4096 + dh0)*64 + r*8] =
            *(const uint4*)&sxh[o][r*8];
    }
    if (do_fz) {
        int o = tid >> 3, k = tid & 7;
#pragma unroll
        for (int q2 = 0; q2 < 2; q2++) {
            u64t zacc = 0ull;
#pragma unroll
            for (int wp = 0; wp < 32; wp++) {
                __half2 h2 = *(const __half2*)&sxh[o][q2*64 + wp*2];
                float2 f = __half22float2(h2);
                fma2(zacc, dup2(f.x), *(const u64t*)&twf[wp*2][k]);
                fma2(zacc, dup2(f.y), *(const u64t*)&twf[wp*2+1][k]);
            }
            float re, im; up2(zacc, re, im);
            g_a[((size_t)(b*CW+o)*4096 + dh0+q2)*MD + k] = make_float2(re, im);
        }
    }
}

// ---------------- fc head via HMMA: fc1(mma) -> gelu -> fc2(scalar) -> tau + stencil ----------------
__global__ void __launch_bounds__(256) k_fc_mma(const float* __restrict__ w1,
                     const float* __restrict__ b1, const float* __restrict__ w2,
                     const float* __restrict__ b2, const float* __restrict__ u,
                     float* __restrict__ tau, float* __restrict__ out, int b) {
    __shared__ unsigned short sx[CW][136];     // x tile [c][pt], fp16 bits, padded
    __shared__ unsigned short sw1p[FCHN][36];  // w1 transposed [h][c], fp16 bits, padded
    __shared__ float w2f[FCHN][6];
    __shared__ float sb1f[FCHN];
    int tid = threadIdx.x;   // 256
    int s0 = blockIdx.x*128; // 128 points per block, grid 2048
    for (int t = tid; t < 512; t += 256) {
        int c = t >> 4, r = t & 15;
        *(uint4*)&sx[c][r*8] =
            *(const uint4*)&g_x0[(((size_t)b*CW + c) << 18) + s0 + r*8];
    }
    for (int t = tid; t < CW*FCHN; t += 256) {
        int c = t >> 7, h = t & 127;
        __half hv = __float2half_rn(w1[c*FCHN + h]);
        sw1p[h][c] = *(unsigned short*)&hv;
    }
    for (int t = tid; t < FCHN*6; t += 256) w2f[t/6][t%6] = w2[t];
    if (tid < FCHN) sb1f[tid] = b1[tid];
    __shared__ float sb2f[6];
    if (tid < 6) sb2f[tid] = b2[tid];
    __syncthreads();

    int wid = tid >> 5, lane = tid & 31;
    int g = lane >> 2, t4 = lane & 3;
    int plo = wid*16 + g, phi = plo + 8;
    u32t afr[2][4];
#pragma unroll
    for (int s = 0; s < 2; s++) {
        int c0 = s*16 + 2*t4;
        afr[s][0] = (u32t)sx[c0][plo]   | ((u32t)sx[c0+1][plo] << 16);
        afr[s][1] = (u32t)sx[c0][phi]   | ((u32t)sx[c0+1][phi] << 16);
        afr[s][2] = (u32t)sx[c0+8][plo] | ((u32t)sx[c0+9][plo] << 16);
        afr[s][3] = (u32t)sx[c0+8][phi] | ((u32t)sx[c0+9][phi] << 16);
    }
    float cf[16][4];
#pragma unroll
    for (int t = 0; t < 16; t++) {
        float bv0 = sb1f[t*8 + 2*t4], bv1 = sb1f[t*8 + 2*t4 + 1];
        cf[t][0] = bv0; cf[t][1] = bv1; cf[t][2] = bv0; cf[t][3] = bv1;
    }
#pragma unroll
    for (int t = 0; t < 16; t++) {
        int n = t*8 + g;
        u32t b00 = *(const u32t*)&sw1p[n][2*t4];
        u32t b01 = *(const u32t*)&sw1p[n][2*t4 + 8];
        mma16816(cf[t], afr[0][0], afr[0][1], afr[0][2], afr[0][3], b00, b01);
        u32t b10 = *(const u32t*)&sw1p[n][2*t4 + 16];
        u32t b11 = *(const u32t*)&sw1p[n][2*t4 + 24];
        mma16816(cf[t], afr[1][0], afr[1][1], afr[1][2], afr[1][3], b10, b11);
    }
    float part[6][2];
#pragma unroll
    for (int o = 0; o < 6; o++) { part[o][0] = sb2f[o]*0.25f; part[o][1] = sb2f[o]*0.25f; }
#pragma unroll
    for (int t = 0; t < 16; t++) {
        int h0 = t*8 + 2*t4, h1 = h0 + 1;
        float d0 = gelu_fast(cf[t][0]);
        float d1 = gelu_fast(cf[t][1]);
        float d2 = gelu_fast(cf[t][2]);
        float d3 = gelu_fast(cf[t][3]);
#pragma unroll
        for (int o = 0; o < 6; o++) {
            float wa = w2f[h0][o], wb = w2f[h1][o];
            part[o][0] += d0*wa + d1*wb;
            part[o][1] += d2*wa + d3*wb;
        }
    }
    float sums[6][2];
#pragma unroll
    for (int o = 0; o < 6; o++) {
#pragma unroll
        for (int r = 0; r < 2; r++) {
            float v = part[o][r];
            v += __shfl_xor_sync(0xffffffffu, v, 1);
            v += __shfl_xor_sync(0xffffffffu, v, 2);
            sums[o][r] = v;
        }
    }
    int sl = s0 + plo, sh = s0 + phi;
    if (t4 < 3) {
#pragma unroll
        for (int r = 0; r < 2; r++) {
            int sp = r ? sh : sl;
            tau[(((size_t)b*6 + t4)     << 18) + sp] = sums[t4][r];
            tau[(((size_t)b*6 + t4 + 3) << 18) + sp] = sums[t4+3][r];
        }
        int i = t4;
        const float dx = 2.0f*3.14159265358979323846f/64.0f;
        const float inv2dx = 1.0f/(2.0f*dx);
        const float invdx2 = 1.0f/(dx*dx);
        const float* ub = u + ((size_t)b*3 << 18);
#pragma unroll
        for (int r = 0; r < 2; r++) {
            int sp = r ? sh : sl;
            int d = sp >> 12, h = (sp >> 6) & 63, w = sp & 63;
            int dp = (((d+1)&63)<<12) | (h<<6) | w;
            int dm = (((d+63)&63)<<12) | (h<<6) | w;
            int hp = (d<<12) | (((h+1)&63)<<6) | w;
            int hm = (d<<12) | (((h+63)&63)<<6) | w;
            int wp = (d<<12) | (h<<6) | ((w+1)&63);
            int wm = (d<<12) | (h<<6) | ((w+63)&63);
            float u0 = ub[(0<<18)+sp], u1 = ub[(1<<18)+sp], u2 = ub[(2<<18)+sp];
            const float* ui = ub + (i<<18);
            float xp = ui[dp], xm = ui[dm];
            float yp = ui[hp], ym = ui[hm];
            float zp = ui[wp], zm = ui[wm];
            float uc = (i == 0) ? u0 : (i == 1) ? u1 : u2;
            float conv = -( u0*(xp-xm) + u1*(yp-ym) + u2*(zp-zm) )*inv2dx;
            float lap  = (xp+xm+yp+ym+zp+zm - 6.f*uc)*invdx2;
            out[((size_t)(b*3+i)<<18) + sp] = conv + 0.000185f*lap + 0.001f*sums[i][r];
        }
    }
}

extern "C" void kernel_launch(void* const* d_in, const int* in_sizes, int n_in,
                              void* d_out, int out_size) {
    (void)in_sizes; (void)n_in; (void)out_size;
    const float* u      = (const float*)d_in[0];
    const float* fc0_w  = (const float*)d_in[1];
    const float* fc0_b  = (const float*)d_in[2];
    const float* spec_w = (const float*)d_in[3];
    const float* w_pw   = (const float*)d_in[4];
    const float* b_pw   = (const float*)d_in[5];
    const float* fc1_w  = (const float*)d_in[6];
    const float* fc1_b  = (const float*)d_in[7];
    const float* fc2_w  = (const float*)d_in[8];
    const float* fc2_b  = (const float*)d_in[9];
    float* out = (float*)d_out;
    float* tau = out + (size_t)BN*3*SP;   // du_dt first, then tau

    cudaStream_t st[BN];
    cudaEvent_t  evR, evD[BN];
    for (int i = 0; i < BN; i++)
        cudaStreamCreateWithFlags(&st[i], cudaStreamNonBlocking);
    cudaEventCreateWithFlags(&evR, cudaEventDisableTiming);
    for (int i = 0; i < BN; i++)
        cudaEventCreateWithFlags(&evD[i], cudaEventDisableTiming);

    k_init<<<4, 256>>>();
    cudaEventRecord(evR, 0);

    for (int b = 0; b < BN; b++) {
        cudaStreamWaitEvent(st[b], evR, 0);
        k_fc0<<<RR*RR, 256, 0, st[b]>>>(u, fc0_w, fc0_b, b);
        for (int l = 0; l < NLY; l++) {
            int flip = l & 1;  // input buffer: 0 -> g_x0, 1 -> g_x1
            k_fy  <<<CW*RR,   128, 0, st[b]>>>(b);
            k_fx  <<<CW*MD,   256, 0, st[b]>>>(b);
            k_spec<<<M2*M2,   256, 0, st[b]>>>(spec_w, l, b);
            k_ix  <<<CW*MD,   256, 0, st[b]>>>(b);
            k_iy  <<<CW*RR,   128, 0, st[b]>>>(b);
            k_layer<<<RR*RR/2, 256, 0, st[b]>>>(w_pw, b_pw, l,
                                                (l < NLY-1) ? 1 : 0, flip,
                                                (l < NLY-1) ? 1 : 0, b);
        }
        k_fc_mma<<<SP/128, 256, 0, st[b]>>>(fc1_w, fc1_b, fc2_w, fc2_b, u, tau, out, b);
        cudaEventRecord(evD[b], st[b]);
        cudaStreamWaitEvent(0, evD[b], 0);
    }

    for (int i = 0; i < BN; i++) cudaStreamDestroy(st[i]);
    cudaEventDestroy(evR);
    for (int i = 0; i < BN; i++) cudaEventDestroy(evD[i]);
}

// round 17
// speedup vs baseline: 1.2130x; 1.0652x over previous
#include <cuda_runtime.h>
#include <cuda_fp16.h>
#include <math.h>

#define BN 4
#define CW 32
#define RR 64
#define SP (RR*RR*RR)        // 262144
#define MD 8
#define M2 16
#define NLY 4
#define FCHN 128
#define PI2_64 0.09817477042468103f   // 2*pi/64

typedef unsigned long long u64t;
typedef unsigned int u32t;

__device__ __forceinline__ u64t pk2(float lo, float hi) {
    u64t r; asm("mov.b64 %0, {%1,%2};" : "=l"(r) : "f"(lo), "f"(hi)); return r;
}
__device__ __forceinline__ u64t dup2(float v) { return pk2(v, v); }
__device__ __forceinline__ void up2(u64t v, float& a, float& b) {
    asm("mov.b64 {%0,%1}, %2;" : "=f"(a), "=f"(b) : "l"(v));
}
__device__ __forceinline__ void fma2(u64t& d, u64t a, u64t b) {
    asm("fma.rn.f32x2 %0, %1, %2, %0;" : "+l"(d) : "l"(a), "l"(b));
}

// ---------------- scratch (static device memory; no allocation) ----------------
__device__ __half  g_x0[BN*CW*SP];              // 67 MB (fp16 activations)
__device__ __half  g_x1[BN*CW*SP];              // 67 MB
__device__ float2 g_a [BN*CW*RR*RR*MD];         // 33.5 MB
__device__ float2 g_b [BN*CW*RR*M2*MD];         // 8.4 MB
__device__ float2 g_ft[BN*CW*M2*M2*MD];         // 2 MB
__device__ float2 g_sf[BN*CW*M2*M2*MD];         // 2 MB

// precomputed twiddle tables
__device__ float2 g_twf_[64*MD];    // fwd z: (c,-s)  [ww][k]
__device__ float  g_crt_[MD*64];    // irfft z coef   [k][ww]
__device__ float  g_cit_[MD*64];
__device__ float2 g_twF_[64*M2];    // fwd y/x: (c,-s) [h][j], ky = j<8?j:j+48
__device__ float2 g_twI_[64*M2];    // inv y/x: (c, s)
// precomputed fp16 weights (constant across call; same rounding as before)
__device__ unsigned short g_wpwh[NLY*CW*CW];   // [layer][o][c]
__device__ unsigned short g_w1h [FCHN*CW];     // [h][c]

__global__ void k_init(const float* __restrict__ wpw, const float* __restrict__ w1) {
    int t = blockIdx.x*blockDim.x + threadIdx.x;
    if (t < 512) {
        int ww = t >> 3, k = t & 7;
        float s, c; sincosf(((ww*k)&63)*PI2_64, &s, &c);
        g_twf_[t] = make_float2(c, -s);
        const float scale = 1.0f/262144.0f;
        g_crt_[k*64+ww] = (k == 0) ? scale : 2.f*scale*c;
        g_cit_[k*64+ww] = (k == 0) ? 0.f   : -2.f*scale*s;
    }
    if (t < 1024) {
        int h = t >> 4, j = t & 15;
        int ky = (j < 8) ? j : j + 48;
        float s, c; sincosf(((ky*h)&63)*PI2_64, &s, &c);
        g_twF_[t] = make_float2(c, -s);
        g_twI_[t] = make_float2(c,  s);
    }
    if (t < NLY*CW*CW) {           // 4096
        int layer = t >> 10, oc = t & 1023;
        int o = oc >> 5, c = oc & 31;
        __half hv = __float2half_rn(wpw[layer*1024 + c*32 + o]);
        g_wpwh[t] = *(unsigned short*)&hv;
    }
    if (t < FCHN*CW) {             // 4096
        int h = t >> 5, c = t & 31;
        __half hv = __float2half_rn(w1[c*FCHN + h]);
        g_w1h[t] = *(unsigned short*)&hv;
    }
}

__device__ __forceinline__ float gelu_fast(float a) {
    float z = 1.5957691216057308f * (a + 0.044715f*a*a*a);
    float e;
    asm("ex2.approx.f32 %0, %1;" : "=f"(e) : "f"(-1.4426950408889634f*z));
    float r;
    asm("rcp.approx.f32 %0, %1;" : "=f"(r) : "f"(1.0f + e));
    return a * r;
}

__device__ __forceinline__ void mma16816(float* d, u32t a0, u32t a1, u32t a2, u32t a3,
                                         u32t b0, u32t b1) {
    asm volatile(
        "mma.sync.aligned.m16n8k16.row.col.f32.f16.f16.f32 "
        "{%0,%1,%2,%3}, {%4,%5,%6,%7}, {%8,%9}, {%0,%1,%2,%3};"
        : "+f"(d[0]), "+f"(d[1]), "+f"(d[2]), "+f"(d[3])
        : "r"(a0), "r"(a1), "r"(a2), "r"(a3), "r"(b0), "r"(b1));
}

// ---------------- fc0 + fused forward-z DFT (per batch) ----------------
__global__ void k_fc0(const float* __restrict__ u, const float* __restrict__ w,
                      const float* __restrict__ bias, int b) {
    __shared__ float  su[3][64];
    __shared__ float  sw[3*CW], sb[CW];
    __shared__ float  sxo[CW][65];
    __shared__ float2 twf[64][MD];
    int tid = threadIdx.x;  // 256
    int dh = blockIdx.x;    // 4096
    for (int t = tid; t < 512; t += 256) ((float2*)twf)[t] = g_twf_[t];
    if (tid < 3*CW) sw[tid] = w[tid];
    if (tid < CW)   sb[tid] = bias[tid];
    if (tid < 192) {
        int j = tid >> 6, ww = tid & 63;
        su[j][ww] = u[((size_t)(b*3+j) << 18) + dh*64 + ww];
    }
    __syncthreads();
    {
        int ww = tid & 63, o0 = (tid >> 6)*8;
#pragma unroll
        for (int oi = 0; oi < 8; oi++) {
            int o = o0 + oi;
            float acc = sb[o] + su[0][ww]*sw[o] + su[1][ww]*sw[CW+o] + su[2][ww]*sw[2*CW+o];
            sxo[o][ww] = acc;
            g_x0[((size_t)(b*CW+o) << 18) + dh*64 + ww] = __float2half_rn(acc);
        }
    }
    __syncthreads();
    {
        int o = tid >> 3, k = tid & 7;
        u64t zacc = 0ull;
#pragma unroll
        for (int ww = 0; ww < 64; ww++)
            fma2(zacc, dup2(sxo[o][ww]), *(const u64t*)&twf[ww][k]);
        float re, im; up2(zacc, re, im);
        g_a[((size_t)((b*CW+o)*4096 + dh))*MD + k] = make_float2(re, im);
    }
}

// ---------------- forward y: 64 -> 16 modes (per (c,d) of one batch) ----------------
__global__ void k_fy(int b) {
    __shared__ float2 sa[64][MD];
    __shared__ float2 tw[64][M2];
    int tid = threadIdx.x;  // 128
    int bcd = b*CW*RR + blockIdx.x;   // grid 2048
    for (int t = tid; t < 512; t += 128)
        ((float4*)tw)[t] = ((const float4*)g_twF_)[t];
    const float2* src = g_a + (size_t)bcd*64*MD;
    for (int i = tid; i < 64*MD; i += 128) sa[i>>3][i&7] = src[i];
    __syncthreads();
    int j = tid >> 3, k = tid & 7;
    float re = 0.f, im = 0.f;
#pragma unroll
    for (int h = 0; h < 64; h++) {
        float2 a = sa[h][k], t = tw[h][j];
        re += a.x*t.x - a.y*t.y;
        im += a.x*t.y + a.y*t.x;
    }
    g_b[((size_t)bcd*M2 + j)*MD + k] = make_float2(re, im);
}

// ---------------- forward x: 64 -> 16 modes (per (c,k) of one batch) ----------------
__global__ void k_fx(int b) {
    __shared__ float2 sa[64][M2];
    __shared__ float2 tw[64][M2];
    int tid = threadIdx.x;  // 256
    int bc = b*CW + (blockIdx.x >> 3), k = blockIdx.x & 7;  // grid 256
    for (int t = tid; t < 512; t += 256)
        ((float4*)tw)[t] = ((const float4*)g_twF_)[t];
    const float2* src = g_b + (size_t)bc*64*M2*MD + k;
    for (int i = tid; i < 64*M2; i += 256) sa[i>>4][i&15] = src[(size_t)i*MD];
    __syncthreads();
    int i_ = tid >> 4, j = tid & 15;
    float re = 0.f, im = 0.f;
#pragma unroll
    for (int d = 0; d < 64; d++) {
        float2 a = sa[d][j], t = tw[d][i_];
        re += a.x*t.x - a.y*t.y;
        im += a.x*t.y + a.y*t.x;
    }
    g_ft[(((size_t)bc*M2 + i_)*M2 + j)*MD + k] = make_float2(re, im);
}

// ---------------- spectral channel mix: block per (i,j) of one batch ----------------
__global__ void k_spec(const float* __restrict__ spw, int layer, int b) {
    __shared__ float2 sa[CW][MD];        // 2 KB
    __shared__ float  red[8][CW][M2];    // 16 KB
    int tid = threadIdx.x;   // 256
    int blk = blockIdx.x;    // 256
    int i = blk >> 4, j = blk & 15;
    int corner = (i >= 8 ? 1 : 0) + (j >= 8 ? 2 : 0);
    int m1 = i & 7, m2 = j & 7;
    {
        int c = tid >> 3, k = tid & 7;
        sa[c][k] = g_ft[(((size_t)(b*CW+c)*M2 + i)*M2 + j)*MD + k];
    }
    __syncthreads();
    int o = tid & 31, cq = tid >> 5;   // cq 0..7
    const float* wbase = spw + ((size_t)(layer*4 + corner)*CW*CW*512
                               + (size_t)(m1*64 + m2*8)) * 2;
    float accr[MD], acci[MD];
#pragma unroll
    for (int k = 0; k < MD; k++) { accr[k] = 0.f; acci[k] = 0.f; }
#pragma unroll
    for (int c4 = 0; c4 < 4; c4++) {
        int c = cq*4 + c4;
        const float4* wv = (const float4*)(wbase + (size_t)(c*32 + o)*1024);
        float4 w0 = wv[0], w1 = wv[1], w2 = wv[2], w3 = wv[3];
        const float4* av = (const float4*)&sa[c][0];
        float4 a0 = av[0], a1 = av[1], a2 = av[2], a3 = av[3];
        accr[0] += a0.x*w0.x - a0.y*w0.y;  acci[0] += a0.x*w0.y + a0.y*w0.x;
        accr[1] += a0.z*w0.z - a0.w*w0.w;  acci[1] += a0.z*w0.w + a0.w*w0.z;
        accr[2] += a1.x*w1.x - a1.y*w1.y;  acci[2] += a1.x*w1.y + a1.y*w1.x;
        accr[3] += a1.z*w1.z - a1.w*w1.w;  acci[3] += a1.z*w1.w + a1.w*w1.z;
        accr[4] += a2.x*w2.x - a2.y*w2.y;  acci[4] += a2.x*w2.y + a2.y*w2.x;
        accr[5] += a2.z*w2.z - a2.w*w2.w;  acci[5] += a2.z*w2.w + a2.w*w2.z;
        accr[6] += a3.x*w3.x - a3.y*w3.y;  acci[6] += a3.x*w3.y + a3.y*w3.x;
        accr[7] += a3.z*w3.z - a3.w*w3.w;  acci[7] += a3.z*w3.w + a3.w*w3.z;
    }
#pragma unroll
    for (int k = 0; k < MD; k++) {
        red[cq][o][2*k]   = accr[k];
        red[cq][o][2*k+1] = acci[k];
    }
    __syncthreads();
    float* gs = (float*)g_sf;
#pragma unroll
    for (int r = 0; r < 2; r++) {
        int idx = r*256 + tid;          // 512 outputs
        int o2 = idx >> 4, v = idx & 15;
        float s = red[0][o2][v] + red[1][o2][v] + red[2][o2][v] + red[3][o2][v]
                + red[4][o2][v] + red[5][o2][v] + red[6][o2][v] + red[7][o2][v];
        gs[((((size_t)(b*CW+o2)*M2 + i)*M2 + j)*MD)*2 + v] = s;
    }
}

// ---------------- inverse x: 16 modes -> 64 (per (o,k) of one batch) ----------------
__global__ void k_ix(int b) {
    __shared__ float2 sa[M2][M2];
    __shared__ float2 tw[64][M2];
    int tid = threadIdx.x;  // 256
    int bo = b*CW + (blockIdx.x >> 3), k = blockIdx.x & 7;  // grid 256
    for (int t = tid; t < 512; t += 256)
        ((float4*)tw)[t] = ((const float4*)g_twI_)[t];
    const float2* src = g_sf + (size_t)bo*M2*M2*MD + k;
    for (int t = tid; t < M2*M2; t += 256) sa[t>>4][t&15] = src[(size_t)t*MD];
    __syncthreads();
    for (int t = tid; t < 64*M2; t += 256) {
        int d = t >> 4, j = t & 15;
        float re = 0.f, im = 0.f;
#pragma unroll
        for (int ii = 0; ii < M2; ii++) {
            float2 a = sa[ii][j], w = tw[d][ii];
            re += a.x*w.x - a.y*w.y;
            im += a.x*w.y + a.y*w.x;
        }
        g_b[(((size_t)bo*64 + d)*M2 + j)*MD + k] = make_float2(re, im);
    }
}

// ---------------- inverse y: 16 modes -> 64 (per (o,d) of one batch) ----------------
__global__ void k_iy(int b) {
    __shared__ float2 sa[M2][MD];
    __shared__ float2 tw[64][M2];
    int tid = threadIdx.x;  // 128
    int bod = b*CW*RR + blockIdx.x;   // grid 2048
    for (int t = tid; t < 512; t += 128)
        ((float4*)tw)[t] = ((const float4*)g_twI_)[t];
    const float2* src = g_b + (size_t)bod*M2*MD;
    for (int t = tid; t < M2*MD; t += 128) sa[t>>3][t&7] = src[t];
    __syncthreads();
    for (int t = tid; t < 64*MD; t += 128) {
        int h = t >> 3, k = t & 7;
        float re = 0.f, im = 0.f;
#pragma unroll
        for (int j = 0; j < M2; j++) {
            float2 a = sa[j][k], w = tw[h][j];
            re += a.x*w.x - a.y*w.y;
            im += a.x*w.y + a.y*w.x;
        }
        g_a[((size_t)bod*64 + h)*MD + k] = make_float2(re, im);
    }
}

// ---------------- layer update: HMMA pointwise + irfft-z + gelu + fwd-z ----------------
__global__ void __launch_bounds__(256) k_layer(const float* __restrict__ bpw,
                        int layer, int do_gelu, int flip, int do_fz, int b) {
    __shared__ unsigned short sxh[CW][136];     // x in [c][pt]; out reused as [o][pt]
    __shared__ unsigned short w1h[CW][36];      // pointwise W transposed [o][c] fp16
    __shared__ float szr[2][MD][CW];            // [q][k][o] 2 KB
    __shared__ float szi[2][MD][CW];            // 2 KB
    __shared__ float crt[MD][64], cit[MD][64];  // 4 KB
    __shared__ float2 twf[64][MD];              // 4 KB
    __shared__ float sbf[CW];
    const __half* __restrict__ xin  = flip ? g_x1 : g_x0;
    __half* __restrict__       xout = flip ? g_x0 : g_x1;
    int tid = threadIdx.x;  // 256
    int dh0 = blockIdx.x*2; // grid 2048
    for (int t = tid; t < 512; t += 256) {
        ((float*)crt)[t] = g_crt_[t];
        ((float*)cit)[t] = g_cit_[t];
        ((float2*)twf)[t] = g_twf_[t];
    }
    for (int t = tid; t < 1024; t += 256) {
        int o = t >> 5, c = t & 31;
        w1h[o][c] = g_wpwh[layer*1024 + t];
    }
    if (tid < CW) sbf[tid] = bpw[layer*CW + tid];
    // x load: row c = 128 halfs = 16 uint4 (uint4 = 8 halfs); 32*16 = 512 over 256 thr
    for (int t = tid; t < 512; t += 256) {
        int c = t >> 4, r = t & 15;
        *(uint4*)&sxh[c][r*8] =
            *(const uint4*)&xin[((size_t)(b*CW+c)*4096 + dh0)*64 + r*8];
    }
    // z modes [q][k][o]
    for (int t = tid; t < 512; t += 256) {
        int o = t >> 4, q = (t >> 3) & 1, k = t & 7;
        float2 z = g_a[((size_t)(b*CW+o)*4096 + dh0+q)*MD + k];
        szr[q][k][o] = z.x; szi[q][k][o] = z.y;
    }
    __syncthreads();
    int wid = tid >> 5, lane = tid & 31;
    int g = lane >> 2, t4 = lane & 3;
    int plo = wid*16 + g, phi = plo + 8;
    int q = wid >> 2;                     // z-line index of this warp's points
    int wwlo = plo & 63, wwhi = phi & 63;
    // A fragments (validated mapping from k_fc_mma)
    u32t afr[2][4];
#pragma unroll
    for (int s = 0; s < 2; s++) {
        int c0 = s*16 + 2*t4;
        afr[s][0] = (u32t)sxh[c0][plo]   | ((u32t)sxh[c0+1][plo] << 16);
        afr[s][1] = (u32t)sxh[c0][phi]   | ((u32t)sxh[c0+1][phi] << 16);
        afr[s][2] = (u32t)sxh[c0+8][plo] | ((u32t)sxh[c0+9][plo] << 16);
        afr[s][3] = (u32t)sxh[c0+8][phi] | ((u32t)sxh[c0+9][phi] << 16);
    }
    float cf[4][4];
#pragma unroll
    for (int nt = 0; nt < 4; nt++) {
        float bv0 = sbf[nt*8 + 2*t4], bv1 = sbf[nt*8 + 2*t4 + 1];
        cf[nt][0] = bv0; cf[nt][1] = bv1; cf[nt][2] = bv0; cf[nt][3] = bv1;
    }
#pragma unroll
    for (int nt = 0; nt < 4; nt++) {
        int n = nt*8 + g;
        u32t b00 = *(const u32t*)&w1h[n][2*t4];
        u32t b01 = *(const u32t*)&w1h[n][2*t4 + 8];
        mma16816(cf[nt], afr[0][0], afr[0][1], afr[0][2], afr[0][3], b00, b01);
        u32t b10 = *(const u32t*)&w1h[n][2*t4 + 16];
        u32t b11 = *(const u32t*)&w1h[n][2*t4 + 24];
        mma16816(cf[nt], afr[1][0], afr[1][1], afr[1][2], afr[1][3], b10, b11);
    }
    // irfft-z contribution on frags (f32x2, lo = row plo, hi = row phi)
    u64t lo[4], hi[4];
#pragma unroll
    for (int nt = 0; nt < 4; nt++) {
        lo[nt] = pk2(cf[nt][0], cf[nt][1]);
        hi[nt] = pk2(cf[nt][2], cf[nt][3]);
    }
#pragma unroll
    for (int k = 0; k < MD; k++) {
        u64t crl = dup2(crt[k][wwlo]), cil = dup2(cit[k][wwlo]);
        u64t crh = dup2(crt[k][wwhi]), cih = dup2(cit[k][wwhi]);
#pragma unroll
        for (int nt = 0; nt < 4; nt++) {
            int o0 = nt*8 + 2*t4;
            u64t zr = *(const u64t*)&szr[q][k][o0];
            u64t zi = *(const u64t*)&szi[q][k][o0];
            fma2(lo[nt], zr, crl); fma2(lo[nt], zi, cil);
            fma2(hi[nt], zr, crh); fma2(hi[nt], zi, cih);
        }
    }
    // gelu + write fp16 outputs into sxh[o][pt] (columns are warp-private)
#pragma unroll
    for (int nt = 0; nt < 4; nt++) {
        int o0 = nt*8 + 2*t4;
        float v0, v1, v2, v3;
        up2(lo[nt], v0, v1);
        up2(hi[nt], v2, v3);
        if (do_gelu) {
            v0 = gelu_fast(v0); v1 = gelu_fast(v1);
            v2 = gelu_fast(v2); v3 = gelu_fast(v3);
        }
        __half h0 = __float2half_rn(v0), h1 = __float2half_rn(v1);
        __half h2 = __float2half_rn(v2), h3 = __float2half_rn(v3);
        sxh[o0  ][plo] = *(unsigned short*)&h0;
        sxh[o0+1][plo] = *(unsigned short*)&h1;
        sxh[o0  ][phi] = *(unsigned short*)&h2;
        sxh[o0+1][phi] = *(unsigned short*)&h3;
    }
    __syncthreads();
    // cooperative global store: row o = 128 halfs = 16 uint4
    for (int t = tid; t < 512; t += 256) {
        int o = t >> 4, r = t & 15;
        *(uint4*)&xout[((size_t)(b*CW+o)*4096 + dh0)*64 + r*8] =
            *(const uint4*)&sxh[o][r*8];
    }
    if (do_fz) {
        int o = tid >> 3, k = tid & 7;
#pragma unroll
        for (int q2 = 0; q2 < 2; q2++) {
            u64t zacc = 0ull;
#pragma unroll
            for (int wp = 0; wp < 32; wp++) {
                __half2 h2 = *(const __half2*)&sxh[o][q2*64 + wp*2];
                float2 f = __half22float2(h2);
                fma2(zacc, dup2(f.x), *(const u64t*)&twf[wp*2][k]);
                fma2(zacc, dup2(f.y), *(const u64t*)&twf[wp*2+1][k]);
            }
            float re, im; up2(zacc, re, im);
            g_a[((size_t)(b*CW+o)*4096 + dh0+q2)*MD + k] = make_float2(re, im);
        }
    }
}

// ---------------- fc head via HMMA: fc1(mma) -> gelu -> fc2(scalar) -> tau + stencil ----------------
__global__ void __launch_bounds__(256) k_fc_mma(
                     const float* __restrict__ b1, const float* __restrict__ w2,
                     const float* __restrict__ b2, const float* __restrict__ u,
                     float* __restrict__ tau, float* __restrict__ out, int b) {
    __shared__ unsigned short sx[CW][136];     // x tile [c][pt], fp16 bits, padded
    __shared__ unsigned short sw1p[FCHN][36];  // w1 transposed [h][c], fp16 bits, padded
    __shared__ float w2f[FCHN][6];
    __shared__ float sb1f[FCHN];
    int tid = threadIdx.x;   // 256
    int s0 = blockIdx.x*128; // 128 points per block, grid 2048
    for (int t = tid; t < 512; t += 256) {
        int c = t >> 4, r = t & 15;
        *(uint4*)&sx[c][r*8] =
            *(const uint4*)&g_x0[(((size_t)b*CW + c) << 18) + s0 + r*8];
    }
    for (int t = tid; t < CW*FCHN; t += 256) {
        int h = t >> 5, c = t & 31;
        sw1p[h][c] = g_w1h[t];
    }
    for (int t = tid; t < FCHN*6; t += 256) w2f[t/6][t%6] = w2[t];
    if (tid < FCHN) sb1f[tid] = b1[tid];
    __shared__ float sb2f[6];
    if (tid < 6) sb2f[tid] = b2[tid];
    __syncthreads();

    int wid = tid >> 5, lane = tid & 31;
    int g = lane >> 2, t4 = lane & 3;
    int plo = wid*16 + g, phi = plo + 8;
    u32t afr[2][4];
#pragma unroll
    for (int s = 0; s < 2; s++) {
        int c0 = s*16 + 2*t4;
        afr[s][0] = (u32t)sx[c0][plo]   | ((u32t)sx[c0+1][plo] << 16);
        afr[s][1] = (u32t)sx[c0][phi]   | ((u32t)sx[c0+1][phi] << 16);
        afr[s][2] = (u32t)sx[c0+8][plo] | ((u32t)sx[c0+9][plo] << 16);
        afr[s][3] = (u32t)sx[c0+8][phi] | ((u32t)sx[c0+9][phi] << 16);
    }
    float cf[16][4];
#pragma unroll
    for (int t = 0; t < 16; t++) {
        float bv0 = sb1f[t*8 + 2*t4], bv1 = sb1f[t*8 + 2*t4 + 1];
        cf[t][0] = bv0; cf[t][1] = bv1; cf[t][2] = bv0; cf[t][3] = bv1;
    }
#pragma unroll
    for (int t = 0; t < 16; t++) {
        int n = t*8 + g;
        u32t b00 = *(const u32t*)&sw1p[n][2*t4];
        u32t b01 = *(const u32t*)&sw1p[n][2*t4 + 8];
        mma16816(cf[t], afr[0][0], afr[0][1], afr[0][2], afr[0][3], b00, b01);
        u32t b10 = *(const u32t*)&sw1p[n][2*t4 + 16];
        u32t b11 = *(const u32t*)&sw1p[n][2*t4 + 24];
        mma16816(cf[t], afr[1][0], afr[1][1], afr[1][2], afr[1][3], b10, b11);
    }
    float part[6][2];
#pragma unroll
    for (int o = 0; o < 6; o++) { part[o][0] = sb2f[o]*0.25f; part[o][1] = sb2f[o]*0.25f; }
#pragma unroll
    for (int t = 0; t < 16; t++) {
        int h0 = t*8 + 2*t4, h1 = h0 + 1;
        float d0 = gelu_fast(cf[t][0]);
        float d1 = gelu_fast(cf[t][1]);
        float d2 = gelu_fast(cf[t][2]);
        float d3 = gelu_fast(cf[t][3]);
#pragma unroll
        for (int o = 0; o < 6; o++) {
            float wa = w2f[h0][o], wb = w2f[h1][o];
            part[o][0] += d0*wa + d1*wb;
            part[o][1] += d2*wa + d3*wb;
        }
    }
    float sums[6][2];
#pragma unroll
    for (int o = 0; o < 6; o++) {
#pragma unroll
        for (int r = 0; r < 2; r++) {
            float v = part[o][r];
            v += __shfl_xor_sync(0xffffffffu, v, 1);
            v += __shfl_xor_sync(0xffffffffu, v, 2);
            sums[o][r] = v;
        }
    }
    int sl = s0 + plo, sh = s0 + phi;
    if (t4 < 3) {
#pragma unroll
        for (int r = 0; r < 2; r++) {
            int sp = r ? sh : sl;
            tau[(((size_t)b*6 + t4)     << 18) + sp] = sums[t4][r];
            tau[(((size_t)b*6 + t4 + 3) << 18) + sp] = sums[t4+3][r];
        }
        int i = t4;
        const float dx = 2.0f*3.14159265358979323846f/64.0f;
        const float inv2dx = 1.0f/(2.0f*dx);
        const float invdx2 = 1.0f/(dx*dx);
        const float* ub = u + ((size_t)b*3 << 18);
#pragma unroll
        for (int r = 0; r < 2; r++) {
            int sp = r ? sh : sl;
            int d = sp >> 12, h = (sp >> 6) & 63, w = sp & 63;
            int dp = (((d+1)&63)<<12) | (h<<6) | w;
            int dm = (((d+63)&63)<<12) | (h<<6) | w;
            int hp = (d<<12) | (((h+1)&63)<<6) | w;
            int hm = (d<<12) | (((h+63)&63)<<6) | w;
            int wp = (d<<12) | (h<<6) | ((w+1)&63);
            int wm = (d<<12) | (h<<6) | ((w+63)&63);
            float u0 = ub[(0<<18)+sp], u1 = ub[(1<<18)+sp], u2 = ub[(2<<18)+sp];
            const float* ui = ub + (i<<18);
            float xp = ui[dp], xm = ui[dm];
            float yp = ui[hp], ym = ui[hm];
            float zp = ui[wp], zm = ui[wm];
            float uc = (i == 0) ? u0 : (i == 1) ? u1 : u2;
            float conv = -( u0*(xp-xm) + u1*(yp-ym) + u2*(zp-zm) )*inv2dx;
            float lap  = (xp+xm+yp+ym+zp+zm - 6.f*uc)*invdx2;
            out[((size_t)(b*3+i)<<18) + sp] = conv + 0.000185f*lap + 0.001f*sums[i][r];
        }
    }
}

extern "C" void kernel_launch(void* const* d_in, const int* in_sizes, int n_in,
                              void* d_out, int out_size) {
    (void)in_sizes; (void)n_in; (void)out_size;
    const float* u      = (const float*)d_in[0];
    const float* fc0_w  = (const float*)d_in[1];
    const float* fc0_b  = (const float*)d_in[2];
    const float* spec_w = (const float*)d_in[3];
    const float* w_pw   = (const float*)d_in[4];
    const float* b_pw   = (const float*)d_in[5];
    const float* fc1_w  = (const float*)d_in[6];
    const float* fc1_b  = (const float*)d_in[7];
    const float* fc2_w  = (const float*)d_in[8];
    const float* fc2_b  = (const float*)d_in[9];
    float* out = (float*)d_out;
    float* tau = out + (size_t)BN*3*SP;   // du_dt first, then tau

    cudaStream_t st[BN];
    cudaEvent_t  evR, evD[BN];
    for (int i = 0; i < BN; i++)
        cudaStreamCreateWithFlags(&st[i], cudaStreamNonBlocking);
    cudaEventCreateWithFlags(&evR, cudaEventDisableTiming);
    for (int i = 0; i < BN; i++)
        cudaEventCreateWithFlags(&evD[i], cudaEventDisableTiming);

    k_init<<<16, 256>>>(w_pw, fc1_w);
    cudaEventRecord(evR, 0);

    for (int b = 0; b < BN; b++) {
        cudaStreamWaitEvent(st[b], evR, 0);
        k_fc0<<<RR*RR, 256, 0, st[b]>>>(u, fc0_w, fc0_b, b);
        for (int l = 0; l < NLY; l++) {
            int flip = l & 1;  // input buffer: 0 -> g_x0, 1 -> g_x1
            k_fy  <<<CW*RR,   128, 0, st[b]>>>(b);
            k_fx  <<<CW*MD,   256, 0, st[b]>>>(b);
            k_spec<<<M2*M2,   256, 0, st[b]>>>(spec_w, l, b);
            k_ix  <<<CW*MD,   256, 0, st[b]>>>(b);
            k_iy  <<<CW*RR,   128, 0, st[b]>>>(b);
            k_layer<<<RR*RR/2, 256, 0, st[b]>>>(b_pw, l,
                                                (l < NLY-1) ? 1 : 0, flip,
                                                (l < NLY-1) ? 1 : 0, b);
        }
        k_fc_mma<<<SP/128, 256, 0, st[b]>>>(fc1_b, fc2_w, fc2_b, u, tau, out, b);
        cudaEventRecord(evD[b], st[b]);
        cudaStreamWaitEvent(0, evD[b], 0);
    }

    for (int i = 0; i < BN; i++) cudaStreamDestroy(st[i]);
    cudaEventDestroy(evR);
    for (int i = 0; i < BN; i++) cudaEventDestroy(evD[i]);
}